// round 1
// baseline (speedup 1.0000x reference)
#include <cuda_runtime.h>

#define IN_SIZE  65536
#define OUT_SIZE 65536
#define NNZ      1048576
#define BATCH    32

// Scratch: transposed x [IN, 32] and transposed accumulator [OUT, 32].
__device__ float g_xt[IN_SIZE * BATCH];
__device__ float g_ot[OUT_SIZE * BATCH];

// Zero the accumulator (graph replays require re-zeroing every launch).
__global__ void zero_ot_kernel() {
    int idx = blockIdx.x * blockDim.x + threadIdx.x;  // 524288 float4 slots
    reinterpret_cast<float4*>(g_ot)[idx] = make_float4(0.f, 0.f, 0.f, 0.f);
}

// Transpose x [B=32, IN] -> g_xt [IN, 32]. Block (32,32), grid IN/32.
__global__ void transpose_in_kernel(const float* __restrict__ x) {
    __shared__ float tile[32][33];
    int col = blockIdx.x * 32 + threadIdx.x;           // IN index
    tile[threadIdx.y][threadIdx.x] = x[threadIdx.y * IN_SIZE + col];
    __syncthreads();
    int n = blockIdx.x * 32 + threadIdx.y;             // IN index
    g_xt[n * 32 + threadIdx.x] = tile[threadIdx.x][threadIdx.y];
}

// Scatter: warp handles 32 edges. Lane e loads edge meta coalesced, then 32
// broadcast iterations do a coalesced 128B gather + 128B RED to L2.
__global__ void scatter_kernel(const float* __restrict__ w,
                               const int* __restrict__ dst,
                               const int* __restrict__ src) {
    int warpId = (blockIdx.x * blockDim.x + threadIdx.x) >> 5;
    int lane   = threadIdx.x & 31;
    int base   = warpId * 32;

    float wv = __ldg(&w[base + lane]);
    int   sv = __ldg(&src[base + lane]);
    int   dv = __ldg(&dst[base + lane]);

    #pragma unroll
    for (int j = 0; j < 32; j++) {
        float wj = __shfl_sync(0xffffffffu, wv, j);
        int   sj = __shfl_sync(0xffffffffu, sv, j);
        int   dj = __shfl_sync(0xffffffffu, dv, j);
        float val = g_xt[sj * 32 + lane];
        atomicAdd(&g_ot[dj * 32 + lane], wj * val);
    }
}

// Transpose g_ot [OUT, 32] -> out [B=32, OUT]. Block (32,32), grid OUT/32.
__global__ void transpose_out_kernel(float* __restrict__ out) {
    __shared__ float tile[32][33];
    int n = blockIdx.x * 32 + threadIdx.y;             // OUT index
    tile[threadIdx.y][threadIdx.x] = g_ot[n * 32 + threadIdx.x];
    __syncthreads();
    int col = blockIdx.x * 32 + threadIdx.x;           // OUT index
    out[threadIdx.y * OUT_SIZE + col] = tile[threadIdx.x][threadIdx.y];
}

extern "C" void kernel_launch(void* const* d_in, const int* in_sizes, int n_in,
                              void* d_out, int out_size) {
    const float* x       = (const float*)d_in[0];
    const float* weights = (const float*)d_in[1];
    const int*   dst_idx = (const int*)d_in[2];
    const int*   src_idx = (const int*)d_in[3];
    float*       out     = (float*)d_out;

    // 1) zero accumulator: 2M floats = 524288 float4
    zero_ot_kernel<<<2048, 256>>>();

    // 2) transpose x into [IN, 32]
    dim3 tb(32, 32);
    transpose_in_kernel<<<IN_SIZE / 32, tb>>>(x);

    // 3) scatter-accumulate: 1M edges, warp per 32 edges -> 32768 warps
    scatter_kernel<<<(NNZ / 32) * 32 / 256, 256>>>(weights, dst_idx, src_idx);

    // 4) transpose accumulator into d_out [B, OUT]
    transpose_out_kernel<<<OUT_SIZE / 32, tb>>>(out);
}

// round 2
// speedup vs baseline: 1.1403x; 1.1403x over previous
#include <cuda_runtime.h>

#define IN_SIZE  65536
#define OUT_SIZE 65536
#define NNZ      1048576
#define BATCH    32

// Scratch: transposed x [IN, 32] and transposed accumulator [OUT, 32].
__device__ float g_xt[IN_SIZE * BATCH];
__device__ float g_ot[OUT_SIZE * BATCH];

// ---------------------------------------------------------------------------
// prep: zero g_ot slice + transpose x [32, IN] -> g_xt [IN, 32].
// Block = 256 threads, tile = 128 input-cols x 32 batch (16KB smem).
// Grid = IN_SIZE/128 = 512.
// ---------------------------------------------------------------------------
__global__ void prep_kernel(const float* __restrict__ x) {
    __shared__ float tile[128][33];
    const int t    = threadIdx.x;
    const int w    = t >> 5;
    const int lane = t & 31;
    const int base = blockIdx.x * 128;   // input-feature offset

    // Zero this block's slice of g_ot: 4096 floats = 1024 float4.
    float4* oz = reinterpret_cast<float4*>(g_ot) + blockIdx.x * 1024;
    const float4 z = make_float4(0.f, 0.f, 0.f, 0.f);
    #pragma unroll
    for (int i = 0; i < 4; i++) oz[t + i * 256] = z;

    // Load phase: warp w covers batch rows b = bb*8 + w; lane strides the
    // 128 columns (coalesced 128B per warp-instruction).
    #pragma unroll
    for (int bb = 0; bb < 4; bb++) {
        const int b = bb * 8 + w;
        #pragma unroll
        for (int i = 0; i < 4; i++) {
            const int n = lane + 32 * i;
            tile[n][b] = x[b * IN_SIZE + base + n];   // bank (n+b)%32: conflict-free
        }
    }
    __syncthreads();

    // Write phase: linear float4 into g_xt.
    float4* xt4 = reinterpret_cast<float4*>(g_xt) + blockIdx.x * 1024;
    #pragma unroll
    for (int i = 0; i < 4; i++) {
        const int g  = t + i * 256;        // float4 index in tile
        const int n  = g >> 3;             // (g*4)/32
        const int b0 = (g * 4) & 31;
        xt4[g] = make_float4(tile[n][b0], tile[n][b0 + 1],
                             tile[n][b0 + 2], tile[n][b0 + 3]);
    }
}

// ---------------------------------------------------------------------------
// Scatter: warp handles 32 edges. Lane e loads edge meta coalesced, then 32
// broadcast iterations each do a coalesced 128B gather + 128B RED to L2.
// ---------------------------------------------------------------------------
__global__ void scatter_kernel(const float* __restrict__ w,
                               const int* __restrict__ dst,
                               const int* __restrict__ src) {
    const int warpId = (blockIdx.x * blockDim.x + threadIdx.x) >> 5;
    const int lane   = threadIdx.x & 31;
    const int base   = warpId * 32;

    const float wv = __ldg(&w[base + lane]);
    const int   sv = __ldg(&src[base + lane]);
    const int   dv = __ldg(&dst[base + lane]);

    #pragma unroll
    for (int j = 0; j < 32; j++) {
        const float wj = __shfl_sync(0xffffffffu, wv, j);
        const int   sj = __shfl_sync(0xffffffffu, sv, j);
        const int   dj = __shfl_sync(0xffffffffu, dv, j);
        const float val = g_xt[sj * 32 + lane];
        atomicAdd(&g_ot[dj * 32 + lane], wj * val);
    }
}

// ---------------------------------------------------------------------------
// finish: transpose g_ot [OUT, 32] -> out [32, OUT].
// Mirror of prep: float4 on the linear (read) side, coalesced scalar writes.
// Grid = OUT_SIZE/128 = 512.
// ---------------------------------------------------------------------------
__global__ void finish_kernel(float* __restrict__ out) {
    __shared__ float tile[128][33];
    const int t    = threadIdx.x;
    const int w    = t >> 5;
    const int lane = t & 31;
    const int base = blockIdx.x * 128;   // output-feature offset

    // Load phase: linear float4 from g_ot (4 independent LDG.128 per thread).
    const float4* ot4 = reinterpret_cast<const float4*>(g_ot) + blockIdx.x * 1024;
    #pragma unroll
    for (int i = 0; i < 4; i++) {
        const int g  = t + i * 256;
        const float4 v = ot4[g];
        const int n  = g >> 3;
        const int b0 = (g * 4) & 31;
        tile[n][b0]     = v.x;
        tile[n][b0 + 1] = v.y;
        tile[n][b0 + 2] = v.z;
        tile[n][b0 + 3] = v.w;
    }
    __syncthreads();

    // Write phase: warp w covers batch rows b = bb*8 + w; lane strides the
    // 128 columns (coalesced 128B per warp-instruction).
    #pragma unroll
    for (int bb = 0; bb < 4; bb++) {
        const int b = bb * 8 + w;
        #pragma unroll
        for (int i = 0; i < 4; i++) {
            const int n = lane + 32 * i;
            out[b * OUT_SIZE + base + n] = tile[n][b];
        }
    }
}

extern "C" void kernel_launch(void* const* d_in, const int* in_sizes, int n_in,
                              void* d_out, int out_size) {
    const float* x       = (const float*)d_in[0];
    const float* weights = (const float*)d_in[1];
    const int*   dst_idx = (const int*)d_in[2];
    const int*   src_idx = (const int*)d_in[3];
    float*       out     = (float*)d_out;

    // 1) transpose x into [IN, 32] + zero accumulator (fused)
    prep_kernel<<<IN_SIZE / 128, 256>>>(x);

    // 2) scatter-accumulate: 1M edges, warp per 32 edges -> 32768 warps
    scatter_kernel<<<NNZ / 32 / 8, 256>>>(weights, dst_idx, src_idx);

    // 3) transpose accumulator into d_out [B, OUT]
    finish_kernel<<<OUT_SIZE / 128, 256>>>(out);
}

// round 4
// speedup vs baseline: 1.2908x; 1.1319x over previous
#include <cuda_runtime.h>

#define IN_SIZE  65536
#define OUT_SIZE 65536
#define NNZ      1048576
#define BATCH    32

// Scratch: transposed x [IN, 32] and transposed accumulator [OUT, 32].
__device__ float g_xt[IN_SIZE * BATCH];
__device__ float g_ot[OUT_SIZE * BATCH];

// ---------------------------------------------------------------------------
// prep: zero g_ot slice + transpose x [32, IN] -> g_xt [IN, 32].
// Tile = 64 input-cols x 32 batch. Block = 256 threads. Grid = 1024.
// ---------------------------------------------------------------------------
__global__ void prep_kernel(const float* __restrict__ x) {
    __shared__ float tile[64][33];
    const int t    = threadIdx.x;
    const int w    = t >> 5;
    const int lane = t & 31;
    const int base = blockIdx.x * 64;   // input-feature offset

    // Zero this block's slice of g_ot: 2048 floats = 512 float4.
    float4* oz = reinterpret_cast<float4*>(g_ot) + blockIdx.x * 512;
    const float4 z = make_float4(0.f, 0.f, 0.f, 0.f);
    oz[t]       = z;
    oz[t + 256] = z;

    // Load: warp w covers batch rows b = bb*8 + w; lanes stride the 64 cols.
    #pragma unroll
    for (int bb = 0; bb < 4; bb++) {
        const int b = bb * 8 + w;
        #pragma unroll
        for (int i = 0; i < 2; i++) {
            const int n = lane + 32 * i;
            tile[n][b] = x[b * IN_SIZE + base + n];  // bank (n+b)%32: conflict-free
        }
    }
    __syncthreads();

    // Store: linear float4 into g_xt.
    float4* xt4 = reinterpret_cast<float4*>(g_xt) + blockIdx.x * 512;
    #pragma unroll
    for (int i = 0; i < 2; i++) {
        const int g  = t + i * 256;
        const int n  = g >> 3;
        const int b0 = (g * 4) & 31;
        xt4[g] = make_float4(tile[n][b0], tile[n][b0 + 1],
                             tile[n][b0 + 2], tile[n][b0 + 3]);
    }
}

// ---------------------------------------------------------------------------
// Scatter: warp handles 32 edges, 4 edges per iteration via float4.
// Lane octet q = lane>>3 owns edge j*4+q; its 8 lanes cover the 32-float
// batch row as 8 float4s. One LDG.128 + one red.global.add.v4 per octet.
// ---------------------------------------------------------------------------
__global__ void scatter_kernel(const float* __restrict__ w,
                               const int* __restrict__ dst,
                               const int* __restrict__ src) {
    const int warpId = (blockIdx.x * blockDim.x + threadIdx.x) >> 5;
    const int lane   = threadIdx.x & 31;
    const int base   = warpId * 32;

    const float wv = __ldg(&w[base + lane]);
    const int   sv = __ldg(&src[base + lane]);
    const int   dv = __ldg(&dst[base + lane]);

    const int q = lane >> 3;   // edge slot within group of 4
    const int r = lane & 7;    // float4 slot within batch row

    #pragma unroll
    for (int j = 0; j < 8; j++) {
        const int   e  = j * 4 + q;
        const float wj = __shfl_sync(0xffffffffu, wv, e);
        const int   sj = __shfl_sync(0xffffffffu, sv, e);
        const int   dj = __shfl_sync(0xffffffffu, dv, e);

        const float4 v = *reinterpret_cast<const float4*>(&g_xt[sj * 32 + r * 4]);
        const float cx = v.x * wj, cy = v.y * wj, cz = v.z * wj, cw = v.w * wj;
        float* p = &g_ot[dj * 32 + r * 4];
        asm volatile("red.global.add.v4.f32 [%0], {%1, %2, %3, %4};"
                     :: "l"(p), "f"(cx), "f"(cy), "f"(cz), "f"(cw)
                     : "memory");
    }
}

// ---------------------------------------------------------------------------
// finish: transpose g_ot [OUT, 32] -> out [32, OUT].
// Tile = 64 output-cols x 32 batch. Block = 256 threads. Grid = 1024.
// ---------------------------------------------------------------------------
__global__ void finish_kernel(float* __restrict__ out) {
    __shared__ float tile[64][33];
    const int t    = threadIdx.x;
    const int w    = t >> 5;
    const int lane = t & 31;
    const int base = blockIdx.x * 64;   // output-feature offset

    // Load: linear float4 from g_ot.
    const float4* ot4 = reinterpret_cast<const float4*>(g_ot) + blockIdx.x * 512;
    #pragma unroll
    for (int i = 0; i < 2; i++) {
        const int g  = t + i * 256;
        const float4 v = ot4[g];
        const int n  = g >> 3;
        const int b0 = (g * 4) & 31;
        tile[n][b0]     = v.x;
        tile[n][b0 + 1] = v.y;
        tile[n][b0 + 2] = v.z;
        tile[n][b0 + 3] = v.w;
    }
    __syncthreads();

    // Store: warp w covers batch rows b = bb*8 + w; lanes stride the 64 cols.
    #pragma unroll
    for (int bb = 0; bb < 4; bb++) {
        const int b = bb * 8 + w;
        #pragma unroll
        for (int i = 0; i < 2; i++) {
            const int n = lane + 32 * i;
            out[b * OUT_SIZE + base + n] = tile[n][b];
        }
    }
}

extern "C" void kernel_launch(void* const* d_in, const int* in_sizes, int n_in,
                              void* d_out, int out_size) {
    const float* x       = (const float*)d_in[0];
    const float* weights = (const float*)d_in[1];
    const int*   dst_idx = (const int*)d_in[2];
    const int*   src_idx = (const int*)d_in[3];
    float*       out     = (float*)d_out;

    // 1) transpose x into [IN, 32] + zero accumulator (fused)
    prep_kernel<<<IN_SIZE / 64, 256>>>(x);

    // 2) scatter-accumulate: 1M edges, warp per 32 edges
    scatter_kernel<<<NNZ / 32 / 8, 256>>>(weights, dst_idx, src_idx);

    // 3) transpose accumulator into d_out [B, OUT]
    finish_kernel<<<OUT_SIZE / 64, 256>>>(out);
}

// round 5
// speedup vs baseline: 1.3194x; 1.0222x over previous
#include <cuda_runtime.h>

#define IN_SIZE  65536
#define OUT_SIZE 65536
#define NNZ      1048576
#define BATCH    32

// Scratch: transposed x [IN, 32] and transposed accumulator [OUT, 32].
__device__ float g_xt[IN_SIZE * BATCH];
__device__ float g_ot[OUT_SIZE * BATCH];

// ---------------------------------------------------------------------------
// prep: zero g_ot slice + transpose x [32, IN] -> g_xt [IN, 32].
// Tile = 64 input-cols x 32 batch, stride-33 smem (conflict-free both phases).
// Block = 256 threads. Grid = 1024. Vectorized: LDG.128 in, STG.128 out.
// ---------------------------------------------------------------------------
__global__ void prep_kernel(const float* __restrict__ x) {
    __shared__ float tile[64][33];
    const int t    = threadIdx.x;
    const int base = blockIdx.x * 64;    // input-feature offset

    // Zero this block's slice of g_ot: 2048 floats = 512 float4.
    float4* oz = reinterpret_cast<float4*>(g_ot) + blockIdx.x * 512;
    const float4 z = make_float4(0.f, 0.f, 0.f, 0.f);
    oz[t]       = z;
    oz[t + 256] = z;

    // Load phase: thread (b = t>>3, j0 = t&7) reads float4 along the feature
    // dim; scalar STS at bank (4*j0 + c + b) -- conflict-free per warp.
    const int b  = t >> 3;
    const int j0 = t & 7;
    #pragma unroll
    for (int i = 0; i < 2; i++) {
        const int j = j0 + 8 * i;        // float4 column 0..15
        const float4 v = *reinterpret_cast<const float4*>(
            &x[b * IN_SIZE + base + 4 * j]);
        tile[4 * j + 0][b] = v.x;
        tile[4 * j + 1][b] = v.y;
        tile[4 * j + 2][b] = v.z;
        tile[4 * j + 3][b] = v.w;
    }
    __syncthreads();

    // Store phase: linear float4 into g_xt (4 LDS + 1 STG.128 each).
    float4* xt4 = reinterpret_cast<float4*>(g_xt) + blockIdx.x * 512;
    #pragma unroll
    for (int i = 0; i < 2; i++) {
        const int g  = t + i * 256;      // float4 index in tile
        const int n  = g >> 3;
        const int b0 = (g * 4) & 31;
        xt4[g] = make_float4(tile[n][b0], tile[n][b0 + 1],
                             tile[n][b0 + 2], tile[n][b0 + 3]);
    }
}

// ---------------------------------------------------------------------------
// Scatter: warp handles 32 edges, 4 edges per iteration via float4.
// Lane octet q = lane>>3 owns edge j*4+q; its 8 lanes cover the 32-float
// batch row as 8 float4s. One LDG.128 + one red.global.add.v4 per octet.
// ---------------------------------------------------------------------------
__global__ void scatter_kernel(const float* __restrict__ w,
                               const int* __restrict__ dst,
                               const int* __restrict__ src) {
    const int warpId = (blockIdx.x * blockDim.x + threadIdx.x) >> 5;
    const int lane   = threadIdx.x & 31;
    const int base   = warpId * 32;

    const float wv = __ldg(&w[base + lane]);
    const int   sv = __ldg(&src[base + lane]);
    const int   dv = __ldg(&dst[base + lane]);

    const int q = lane >> 3;   // edge slot within group of 4
    const int r = lane & 7;    // float4 slot within batch row

    #pragma unroll
    for (int j = 0; j < 8; j++) {
        const int   e  = j * 4 + q;
        const float wj = __shfl_sync(0xffffffffu, wv, e);
        const int   sj = __shfl_sync(0xffffffffu, sv, e);
        const int   dj = __shfl_sync(0xffffffffu, dv, e);

        const float4 v = *reinterpret_cast<const float4*>(&g_xt[sj * 32 + r * 4]);
        const float cx = v.x * wj, cy = v.y * wj, cz = v.z * wj, cw = v.w * wj;
        float* p = &g_ot[dj * 32 + r * 4];
        asm volatile("red.global.add.v4.f32 [%0], {%1, %2, %3, %4};"
                     :: "l"(p), "f"(cx), "f"(cy), "f"(cz), "f"(cw)
                     : "memory");
    }
}

// ---------------------------------------------------------------------------
// finish: transpose g_ot [OUT, 32] -> out [32, OUT].
// Mirror of prep: LDG.128 from g_ot, STG.128 to out. Grid = 1024.
// ---------------------------------------------------------------------------
__global__ void finish_kernel(float* __restrict__ out) {
    __shared__ float tile[64][33];
    const int t    = threadIdx.x;
    const int base = blockIdx.x * 64;    // output-feature offset

    // Load phase: linear float4 from g_ot; scalar STS (conflict-free).
    const float4* ot4 = reinterpret_cast<const float4*>(g_ot) + blockIdx.x * 512;
    #pragma unroll
    for (int i = 0; i < 2; i++) {
        const int g  = t + i * 256;
        const float4 v = ot4[g];
        const int n  = g >> 3;
        const int b0 = (g * 4) & 31;
        tile[n][b0]     = v.x;
        tile[n][b0 + 1] = v.y;
        tile[n][b0 + 2] = v.z;
        tile[n][b0 + 3] = v.w;
    }
    __syncthreads();

    // Store phase: thread (b = t>>3, j0 = t&7) gathers 4 scalars from smem
    // (bank 4*j0 + c + b -- conflict-free) and writes one float4 to out.
    const int b  = t >> 3;
    const int j0 = t & 7;
    #pragma unroll
    for (int i = 0; i < 2; i++) {
        const int j = j0 + 8 * i;
        const float4 r = make_float4(tile[4 * j + 0][b], tile[4 * j + 1][b],
                                     tile[4 * j + 2][b], tile[4 * j + 3][b]);
        *reinterpret_cast<float4*>(&out[b * OUT_SIZE + base + 4 * j]) = r;
    }
}

extern "C" void kernel_launch(void* const* d_in, const int* in_sizes, int n_in,
                              void* d_out, int out_size) {
    const float* x       = (const float*)d_in[0];
    const float* weights = (const float*)d_in[1];
    const int*   dst_idx = (const int*)d_in[2];
    const int*   src_idx = (const int*)d_in[3];
    float*       out     = (float*)d_out;

    // 1) transpose x into [IN, 32] + zero accumulator (fused)
    prep_kernel<<<IN_SIZE / 64, 256>>>(x);

    // 2) scatter-accumulate: 1M edges, warp per 32 edges
    scatter_kernel<<<NNZ / 32 / 8, 256>>>(weights, dst_idx, src_idx);

    // 3) transpose accumulator into d_out [B, OUT]
    finish_kernel<<<OUT_SIZE / 64, 256>>>(out);
}